// round 7
// baseline (speedup 1.0000x reference)
#include <cuda_runtime.h>
#include <math.h>
#include <stdint.h>

#define DM   1024
#define NTOK 4096
#define SEQ  2048
#define NH   16

// Scratch (allocation-free rule: __device__ globals)
__device__ float g_Xn[NTOK * DM];
__device__ float g_Q [NTOK * DM];
__device__ float g_K [NTOK * DM];
__device__ float g_V [NTOK * DM];
__device__ float g_M [NTOK * DM];
__device__ float g_Wr[4 * DM * DM];   // pre-rounded (tf32 RNE) Wq|Wk|Wv|Wo

// ---------------------------------------------------------------------------
// helpers
// ---------------------------------------------------------------------------
__device__ __forceinline__ uint32_t smem_u32(const void* p) {
    uint32_t a;
    asm("{ .reg .u64 t; cvta.to.shared.u64 t, %1; cvt.u32.u64 %0, t; }" : "=r"(a) : "l"(p));
    return a;
}
__device__ __forceinline__ uint32_t tf32u(float x) {
    uint32_t u; asm("cvt.rna.tf32.f32 %0, %1;" : "=r"(u) : "f"(x));
    return u;
}
__device__ __forceinline__ float tf32f(float x) { return __uint_as_float(tf32u(x)); }

__device__ __forceinline__ void mma_tf32(float* d, const uint32_t* a,
                                         uint32_t b0, uint32_t b1) {
    asm volatile(
        "mma.sync.aligned.m16n8k8.row.col.f32.tf32.tf32.f32 "
        "{%0,%1,%2,%3}, {%4,%5,%6,%7}, {%8,%9}, {%0,%1,%2,%3};"
        : "+f"(d[0]), "+f"(d[1]), "+f"(d[2]), "+f"(d[3])
        : "r"(a[0]), "r"(a[1]), "r"(a[2]), "r"(a[3]), "r"(b0), "r"(b1));
}

#define CP_ASYNC16(dst, src) \
    asm volatile("cp.async.cg.shared.global [%0], [%1], 16;" :: "r"(dst), "l"(src) : "memory")
#define CP_COMMIT() asm volatile("cp.async.commit_group;" ::: "memory")
#define CP_WAIT(n)  asm volatile("cp.async.wait_group %0;" :: "n"(n) : "memory")

// ---------------------------------------------------------------------------
// LayerNorm (tf32-rounded output: feeds tf32 MMAs)
// ---------------------------------------------------------------------------
__global__ void ln_kernel(const float* __restrict__ X, const float* __restrict__ w,
                          const float* __restrict__ b, float* __restrict__ out) {
    int row = blockIdx.x;
    int t = threadIdx.x;
    const float4* xr = reinterpret_cast<const float4*>(X + (size_t)row * DM);
    float4 v = xr[t];
    float s  = v.x + v.y + v.z + v.w;
    float s2 = v.x * v.x + v.y * v.y + v.z * v.z + v.w * v.w;
    __shared__ float rs[8], rs2[8];
#pragma unroll
    for (int o = 16; o > 0; o >>= 1) {
        s  += __shfl_xor_sync(0xffffffffu, s,  o);
        s2 += __shfl_xor_sync(0xffffffffu, s2, o);
    }
    if ((t & 31) == 0) { rs[t >> 5] = s; rs2[t >> 5] = s2; }
    __syncthreads();
    float S = 0.f, S2 = 0.f;
#pragma unroll
    for (int i = 0; i < 8; i++) { S += rs[i]; S2 += rs2[i]; }
    float mu  = S * (1.0f / DM);
    float var = S2 * (1.0f / DM) - mu * mu;
    float inv = rsqrtf(var + 1e-4f);
    float4 wv = reinterpret_cast<const float4*>(w)[t];
    float4 bv = reinterpret_cast<const float4*>(b)[t];
    float4 o;
    o.x = tf32f((v.x - mu) * inv * wv.x + bv.x);
    o.y = tf32f((v.y - mu) * inv * wv.y + bv.y);
    o.z = tf32f((v.z - mu) * inv * wv.z + bv.z);
    o.w = tf32f((v.w - mu) * inv * wv.w + bv.w);
    reinterpret_cast<float4*>(out + (size_t)row * DM)[t] = o;
}

// ---------------------------------------------------------------------------
// One launch: RNE-round all four weight matrices into g_Wr
// ---------------------------------------------------------------------------
__global__ void __launch_bounds__(256)
round4_tf32(const float* __restrict__ W0, const float* __restrict__ W1,
            const float* __restrict__ W2, const float* __restrict__ W3,
            float* __restrict__ R) {
    int i = blockIdx.x * 256 + threadIdx.x;       // float4 index, 4*DM*DM/4 total
    int which = i >> 18;                          // DM*DM/4 = 262144 per matrix
    int j = i & 262143;
    const float* W = (which == 0) ? W0 : (which == 1) ? W1 : (which == 2) ? W2 : W3;
    float4 v = reinterpret_cast<const float4*>(W)[j];
    float4 o = { tf32f(v.x), tf32f(v.y), tf32f(v.z), tf32f(v.w) };
    reinterpret_cast<float4*>(R)[i] = o;
}

// ---------------------------------------------------------------------------
// tf32 mma.sync GEMM, up to 3 (pre-rounded) weight matrices fused.
// C[4096,1024] = A @ W + bias. 128x128x32 tiles, 8 warps, cp.async dbl buffer.
// ---------------------------------------------------------------------------
#define APAD 36
#define BPAD 136
#define A_ST (128 * APAD)
#define B_ST (32 * BPAD)
#define GEMM_SMEM ((2 * (A_ST + B_ST)) * 4)   // 71680 B

__global__ void __launch_bounds__(256)
gemm_mma3(const float* __restrict__ A,
          const float* __restrict__ W0, const float* __restrict__ W1,
          const float* __restrict__ W2,
          const float* __restrict__ bi0, const float* __restrict__ bi1,
          const float* __restrict__ bi2,
          float* __restrict__ C0, float* __restrict__ C1, float* __restrict__ C2) {
    extern __shared__ __align__(16) float sm[];
    float* Asm[2] = { sm, sm + A_ST };
    float* Bsm[2] = { sm + 2 * A_ST, sm + 2 * A_ST + B_ST };
    uint32_t aAddr[2] = { smem_u32(Asm[0]), smem_u32(Asm[1]) };
    uint32_t bAddr[2] = { smem_u32(Bsm[0]), smem_u32(Bsm[1]) };

    int nb = blockIdx.x;
    int sel = nb >> 3;
    int n0 = (nb & 7) * 128;
    const float* W    = (sel == 0) ? W0 : (sel == 1) ? W1 : W2;
    const float* bias = (sel == 0) ? bi0 : (sel == 1) ? bi1 : bi2;
    float* C          = (sel == 0) ? C0 : (sel == 1) ? C1 : C2;

    int tid = threadIdx.x, lane = tid & 31, wid = tid >> 5;
    int r = lane >> 2, cg = lane & 3;
    int wm = wid & 1, wn = wid >> 1;
    int m0 = blockIdx.y * 128;

    float acc[4][4][4];
#pragma unroll
    for (int i = 0; i < 4; i++)
#pragma unroll
        for (int j = 0; j < 4; j++)
#pragma unroll
            for (int k = 0; k < 4; k++) acc[i][j][k] = 0.f;

    auto load_tile = [&](int t, int buf) {
        int k0 = t * 32;
#pragma unroll
        for (int i = 0; i < 4; i++) {
            int idx = i * 256 + tid;
            int row = idx >> 3, c4 = (idx & 7) << 2;
            uint32_t dst = aAddr[buf] + (uint32_t)(row * APAD + c4) * 4u;
            CP_ASYNC16(dst, A + (size_t)(m0 + row) * DM + k0 + c4);
        }
#pragma unroll
        for (int i = 0; i < 4; i++) {
            int idx = i * 256 + tid;
            int row = idx >> 5, c4 = (idx & 31) << 2;
            uint32_t dst = bAddr[buf] + (uint32_t)(row * BPAD + c4) * 4u;
            CP_ASYNC16(dst, W + (size_t)(k0 + row) * DM + n0 + c4);
        }
        CP_COMMIT();
    };

    load_tile(0, 0);
    const int NT = DM / 32;
    for (int t = 0; t < NT; t++) {
        int buf = t & 1;
        if (t + 1 < NT) { load_tile(t + 1, (t + 1) & 1); CP_WAIT(1); }
        else            { CP_WAIT(0); }
        __syncthreads();

        const uint32_t* As = reinterpret_cast<const uint32_t*>(Asm[buf]);
        const uint32_t* Bs = reinterpret_cast<const uint32_t*>(Bsm[buf]);
#pragma unroll
        for (int kk = 0; kk < 4; kk++) {
            int kb = kk * 8;
            uint32_t aF[4][4];
#pragma unroll
            for (int mt = 0; mt < 4; mt++) {
                int mr = wm * 64 + mt * 16 + r;
                aF[mt][0] = As[mr * APAD + kb + cg];
                aF[mt][1] = As[(mr + 8) * APAD + kb + cg];
                aF[mt][2] = As[mr * APAD + kb + cg + 4];
                aF[mt][3] = As[(mr + 8) * APAD + kb + cg + 4];
            }
            uint32_t bF[4][2];
#pragma unroll
            for (int nt = 0; nt < 4; nt++) {
                int nc = wn * 32 + nt * 8 + r;
                bF[nt][0] = Bs[(kb + cg) * BPAD + nc];
                bF[nt][1] = Bs[(kb + cg + 4) * BPAD + nc];
            }
#pragma unroll
            for (int mt = 0; mt < 4; mt++)
#pragma unroll
                for (int nt = 0; nt < 4; nt++)
                    mma_tf32(acc[mt][nt], aF[mt], bF[nt][0], bF[nt][1]);
        }
        __syncthreads();
    }

    const float* bp = bias + n0 + wn * 32;
#pragma unroll
    for (int nt = 0; nt < 4; nt++) {
        float2 bb = *reinterpret_cast<const float2*>(bp + nt * 8 + 2 * cg);
#pragma unroll
        for (int mt = 0; mt < 4; mt++) {
            int row = m0 + wm * 64 + mt * 16 + r;
            float* c0 = C + (size_t)row * DM + n0 + wn * 32 + nt * 8 + 2 * cg;
            float* c1 = C + (size_t)(row + 8) * DM + n0 + wn * 32 + nt * 8 + 2 * cg;
            float2 v0 = { acc[mt][nt][0] + bb.x, acc[mt][nt][1] + bb.y };
            float2 v1 = { acc[mt][nt][2] + bb.x, acc[mt][nt][3] + bb.y };
            *reinterpret_cast<float2*>(c0) = v0;
            *reinterpret_cast<float2*>(c1) = v1;
        }
    }
}

// ---------------------------------------------------------------------------
// Flash attention, mma.sync tf32. 256 threads (8 warps), q-tile 128, k-tile 64.
// cp.async double-buffered K/V (raw) + in-place tf32 convert.
// ---------------------------------------------------------------------------
#define ATT_PAD 68
#define KV_ST (64 * ATT_PAD)
#define ATTN_SMEM ((4 * 64 + 128) * ATT_PAD * 4)   // 2xK + 2xV + Ps = 104448 B

__global__ void __launch_bounds__(256)
attn_mma(const float* __restrict__ Q, const float* __restrict__ K,
         const float* __restrict__ V, float* __restrict__ O) {
    extern __shared__ __align__(16) float sm[];
    float* Kb[2] = { sm, sm + KV_ST };
    float* Vb[2] = { sm + 2 * KV_ST, sm + 3 * KV_ST };
    float* Ps = sm + 4 * KV_ST;
    uint32_t kAddr[2] = { smem_u32(Kb[0]), smem_u32(Kb[1]) };
    uint32_t vAddr[2] = { smem_u32(Vb[0]), smem_u32(Vb[1]) };
    const uint32_t* PsU = reinterpret_cast<const uint32_t*>(Ps);

    int tid = threadIdx.x, lane = tid & 31, wid = tid >> 5;
    int qt = gridDim.x - 1 - blockIdx.x;          // heavy tiles first
    int bh = blockIdx.y;
    int b = bh >> 4, h = bh & 15, cb = h << 6;
    int qbase = b * SEQ + (qt << 7);
    int r = lane >> 2, cg = lane & 3;
    int qrow = (wid << 4) + r;                    // block-local 0..127 (+8)

    // Q fragments (scaled, tf32-rounded) — one-time load
    uint32_t aQ[8][4];
    const float* Q0 = Q + (size_t)(qbase + qrow) * DM + cb;
    const float* Q1 = Q + (size_t)(qbase + qrow + 8) * DM + cb;
#pragma unroll
    for (int kk = 0; kk < 8; kk++) {
        aQ[kk][0] = tf32u(Q0[kk * 8 + cg] * 0.125f);
        aQ[kk][1] = tf32u(Q1[kk * 8 + cg] * 0.125f);
        aQ[kk][2] = tf32u(Q0[kk * 8 + cg + 4] * 0.125f);
        aQ[kk][3] = tf32u(Q1[kk * 8 + cg + 4] * 0.125f);
    }

    float m0 = -INFINITY, m1 = -INFINITY, l0 = 0.f, l1 = 0.f;
    float oc[8][4];
#pragma unroll
    for (int i = 0; i < 8; i++)
#pragma unroll
        for (int j = 0; j < 4; j++) oc[i][j] = 0.f;

    auto prefetch = [&](int kt, int buf) {
        const float* Kg = K + (size_t)(b * SEQ + (kt << 6)) * DM + cb;
        const float* Vg = V + (size_t)(b * SEQ + (kt << 6)) * DM + cb;
#pragma unroll
        for (int i = 0; i < 4; i++) {
            int idx = i * 256 + tid;
            int row = idx >> 4, d4 = (idx & 15) << 2;
            uint32_t so = (uint32_t)(row * ATT_PAD + d4) * 4u;
            CP_ASYNC16(kAddr[buf] + so, Kg + (size_t)row * DM + d4);
            CP_ASYNC16(vAddr[buf] + so, Vg + (size_t)row * DM + d4);
        }
        CP_COMMIT();
    };

    int ktmax = 2 * qt + 1;
    prefetch(0, 0);
    for (int kt = 0; kt <= ktmax; kt++) {
        int buf = kt & 1;
        __syncthreads();   // all warps done reading buf (tile kt-2) and Ps
        if (kt < ktmax) { prefetch(kt + 1, buf ^ 1); CP_WAIT(1); }
        else            { CP_WAIT(0); }
        __syncthreads();   // tile kt data visible to all

        // in-place RNE tf32 convert of this tile
#pragma unroll
        for (int i = 0; i < 4; i++) {
            int idx = i * 256 + tid;
            int row = idx >> 4, d4 = (idx & 15) << 2;
            float4* kp = reinterpret_cast<float4*>(Kb[buf] + row * ATT_PAD + d4);
            float4* vp = reinterpret_cast<float4*>(Vb[buf] + row * ATT_PAD + d4);
            float4 kv = *kp, vv = *vp;
            *kp = { tf32f(kv.x), tf32f(kv.y), tf32f(kv.z), tf32f(kv.w) };
            *vp = { tf32f(vv.x), tf32f(vv.y), tf32f(vv.z), tf32f(vv.w) };
        }
        __syncthreads();

        // warps whose 16 rows are entirely above this k-tile: fully masked, skip
        bool active = ((kt << 6) <= (qt << 7) + (wid << 4) + 15);
        if (!active) continue;

        const uint32_t* KsU = reinterpret_cast<const uint32_t*>(Kb[buf]);
        const uint32_t* VsU = reinterpret_cast<const uint32_t*>(Vb[buf]);

        // S = Q K^T
        float sc[8][4];
#pragma unroll
        for (int nt = 0; nt < 8; nt++) {
#pragma unroll
            for (int j = 0; j < 4; j++) sc[nt][j] = 0.f;
#pragma unroll
            for (int kk = 0; kk < 8; kk++) {
                uint32_t b0 = KsU[(nt * 8 + r) * ATT_PAD + kk * 8 + cg];
                uint32_t b1 = KsU[(nt * 8 + r) * ATT_PAD + kk * 8 + cg + 4];
                mma_tf32(sc[nt], aQ[kk], b0, b1);
            }
        }

        // causal mask (q-local coords)
        int cofs = (kt << 6) - (qt << 7);
        if (cofs + 63 > qrow) {
#pragma unroll
            for (int nt = 0; nt < 8; nt++) {
                int col = cofs + nt * 8 + 2 * cg;
                if (col > qrow)         sc[nt][0] = -INFINITY;
                if (col + 1 > qrow)     sc[nt][1] = -INFINITY;
                if (col > qrow + 8)     sc[nt][2] = -INFINITY;
                if (col + 1 > qrow + 8) sc[nt][3] = -INFINITY;
            }
        }

        // online softmax, quad reduction
        float mx0 = -INFINITY, mx1 = -INFINITY;
#pragma unroll
        for (int nt = 0; nt < 8; nt++) {
            mx0 = fmaxf(mx0, fmaxf(sc[nt][0], sc[nt][1]));
            mx1 = fmaxf(mx1, fmaxf(sc[nt][2], sc[nt][3]));
        }
        mx0 = fmaxf(mx0, __shfl_xor_sync(0xffffffffu, mx0, 1));
        mx0 = fmaxf(mx0, __shfl_xor_sync(0xffffffffu, mx0, 2));
        mx1 = fmaxf(mx1, __shfl_xor_sync(0xffffffffu, mx1, 1));
        mx1 = fmaxf(mx1, __shfl_xor_sync(0xffffffffu, mx1, 2));
        float mn0 = fmaxf(m0, mx0), mn1 = fmaxf(m1, mx1);
        float e0 = __expf(m0 - mn0), e1 = __expf(m1 - mn1);
        float s0 = 0.f, s1 = 0.f;
#pragma unroll
        for (int nt = 0; nt < 8; nt++) {
            sc[nt][0] = __expf(sc[nt][0] - mn0);
            sc[nt][1] = __expf(sc[nt][1] - mn0);
            sc[nt][2] = __expf(sc[nt][2] - mn1);
            sc[nt][3] = __expf(sc[nt][3] - mn1);
            s0 += sc[nt][0] + sc[nt][1];
            s1 += sc[nt][2] + sc[nt][3];
        }
        s0 += __shfl_xor_sync(0xffffffffu, s0, 1);
        s0 += __shfl_xor_sync(0xffffffffu, s0, 2);
        s1 += __shfl_xor_sync(0xffffffffu, s1, 1);
        s1 += __shfl_xor_sync(0xffffffffu, s1, 2);
        l0 = l0 * e0 + s0; m0 = mn0;
        l1 = l1 * e1 + s1; m1 = mn1;
#pragma unroll
        for (int dt = 0; dt < 8; dt++) {
            oc[dt][0] *= e0; oc[dt][1] *= e0;
            oc[dt][2] *= e1; oc[dt][3] *= e1;
        }

        // stage P (tf32-rounded); warp-private rows -> __syncwarp suffices
#pragma unroll
        for (int nt = 0; nt < 8; nt++) {
            float2 p0 = { tf32f(sc[nt][0]), tf32f(sc[nt][1]) };
            float2 p1 = { tf32f(sc[nt][2]), tf32f(sc[nt][3]) };
            *reinterpret_cast<float2*>(Ps + qrow * ATT_PAD + nt * 8 + 2 * cg) = p0;
            *reinterpret_cast<float2*>(Ps + (qrow + 8) * ATT_PAD + nt * 8 + 2 * cg) = p1;
        }
        __syncwarp();

        // O += P @ V
#pragma unroll
        for (int kk = 0; kk < 8; kk++) {
            uint32_t aP[4];
            aP[0] = PsU[qrow * ATT_PAD + kk * 8 + cg];
            aP[1] = PsU[(qrow + 8) * ATT_PAD + kk * 8 + cg];
            aP[2] = PsU[qrow * ATT_PAD + kk * 8 + cg + 4];
            aP[3] = PsU[(qrow + 8) * ATT_PAD + kk * 8 + cg + 4];
#pragma unroll
            for (int dt = 0; dt < 8; dt++) {
                uint32_t b0 = VsU[(kk * 8 + cg) * ATT_PAD + dt * 8 + r];
                uint32_t b1 = VsU[(kk * 8 + cg + 4) * ATT_PAD + dt * 8 + r];
                mma_tf32(oc[dt], aP, b0, b1);
            }
        }
    }

    float inv0 = 1.0f / l0, inv1 = 1.0f / l1;
    float* O0 = O + (size_t)(qbase + qrow) * DM + cb;
    float* O1 = O + (size_t)(qbase + qrow + 8) * DM + cb;
#pragma unroll
    for (int dt = 0; dt < 8; dt++) {
        float2 v0 = { tf32f(oc[dt][0] * inv0), tf32f(oc[dt][1] * inv0) };
        float2 v1 = { tf32f(oc[dt][2] * inv1), tf32f(oc[dt][3] * inv1) };
        *reinterpret_cast<float2*>(O0 + dt * 8 + 2 * cg) = v0;
        *reinterpret_cast<float2*>(O1 + dt * 8 + 2 * cg) = v1;
    }
}

// ---------------------------------------------------------------------------
extern "C" void kernel_launch(void* const* d_in, const int* in_sizes, int n_in,
                              void* d_out, int out_size) {
    const float* X   = (const float*)d_in[0];
    const float* lnw = (const float*)d_in[1];
    const float* lnb = (const float*)d_in[2];
    const float* Wq  = (const float*)d_in[3];
    const float* bq  = (const float*)d_in[4];
    const float* Wk  = (const float*)d_in[5];
    const float* bk  = (const float*)d_in[6];
    const float* Wv  = (const float*)d_in[7];
    const float* bv  = (const float*)d_in[8];
    const float* Wo  = (const float*)d_in[9];
    const float* bo  = (const float*)d_in[10];
    float* out = (float*)d_out;
    (void)in_sizes; (void)n_in; (void)out_size;

    float *Xn, *Qb, *Kb, *Vb, *Mb, *Wr;
    cudaGetSymbolAddress((void**)&Xn, g_Xn);
    cudaGetSymbolAddress((void**)&Qb, g_Q);
    cudaGetSymbolAddress((void**)&Kb, g_K);
    cudaGetSymbolAddress((void**)&Vb, g_V);
    cudaGetSymbolAddress((void**)&Mb, g_M);
    cudaGetSymbolAddress((void**)&Wr, g_Wr);

    cudaFuncSetAttribute(gemm_mma3, cudaFuncAttributeMaxDynamicSharedMemorySize,
                         GEMM_SMEM);
    cudaFuncSetAttribute(attn_mma, cudaFuncAttributeMaxDynamicSharedMemorySize,
                         ATTN_SMEM);

    ln_kernel<<<NTOK, 256>>>(X, lnw, lnb, Xn);
    round4_tf32<<<4 * DM * DM / (256 * 4), 256>>>(Wq, Wk, Wv, Wo, Wr);

    // fused Q,K,V projections (pre-rounded weights)
    gemm_mma3<<<dim3(24, NTOK / 128), 256, GEMM_SMEM>>>(
        Xn, Wr, Wr + DM * DM, Wr + 2 * DM * DM, bq, bk, bv, Qb, Kb, Vb);

    attn_mma<<<dim3(SEQ / 128, 2 * NH), 256, ATTN_SMEM>>>(Qb, Kb, Vb, Mb);

    // output projection (sel always 0)
    gemm_mma3<<<dim3(8, NTOK / 128), 256, GEMM_SMEM>>>(
        Mb, Wr + 3 * DM * DM, Wr + 3 * DM * DM, Wr + 3 * DM * DM,
        bo, bo, bo, out, out, out);
}

// round 8
// speedup vs baseline: 1.0593x; 1.0593x over previous
#include <cuda_runtime.h>
#include <math.h>
#include <stdint.h>

#define DM   1024
#define NTOK 4096
#define SEQ  2048
#define NH   16

// Scratch (allocation-free rule: __device__ globals)
__device__ float g_Xn[NTOK * DM];
__device__ float g_Q [NTOK * DM];
__device__ float g_K [NTOK * DM];
__device__ float g_V [NTOK * DM];
__device__ float g_M [NTOK * DM];
__device__ float g_Wr[4 * DM * DM];   // pre-rounded (tf32 RNE) Wq|Wk|Wv|Wo

// ---------------------------------------------------------------------------
// helpers
// ---------------------------------------------------------------------------
__device__ __forceinline__ uint32_t smem_u32(const void* p) {
    uint32_t a;
    asm("{ .reg .u64 t; cvta.to.shared.u64 t, %1; cvt.u32.u64 %0, t; }" : "=r"(a) : "l"(p));
    return a;
}
__device__ __forceinline__ uint32_t tf32u(float x) {
    uint32_t u; asm("cvt.rna.tf32.f32 %0, %1;" : "=r"(u) : "f"(x));
    return u;
}
__device__ __forceinline__ float tf32f(float x) { return __uint_as_float(tf32u(x)); }

__device__ __forceinline__ void mma_tf32(float* d, const uint32_t* a,
                                         uint32_t b0, uint32_t b1) {
    asm volatile(
        "mma.sync.aligned.m16n8k8.row.col.f32.tf32.tf32.f32 "
        "{%0,%1,%2,%3}, {%4,%5,%6,%7}, {%8,%9}, {%0,%1,%2,%3};"
        : "+f"(d[0]), "+f"(d[1]), "+f"(d[2]), "+f"(d[3])
        : "r"(a[0]), "r"(a[1]), "r"(a[2]), "r"(a[3]), "r"(b0), "r"(b1));
}

#define CP_ASYNC16(dst, src) \
    asm volatile("cp.async.cg.shared.global [%0], [%1], 16;" :: "r"(dst), "l"(src) : "memory")
#define CP_COMMIT() asm volatile("cp.async.commit_group;" ::: "memory")
#define CP_WAIT(n)  asm volatile("cp.async.wait_group %0;" :: "n"(n) : "memory")

// ---------------------------------------------------------------------------
// LayerNorm (tf32-rounded output: feeds tf32 MMAs)
// ---------------------------------------------------------------------------
__global__ void ln_kernel(const float* __restrict__ X, const float* __restrict__ w,
                          const float* __restrict__ b, float* __restrict__ out) {
    int row = blockIdx.x;
    int t = threadIdx.x;
    const float4* xr = reinterpret_cast<const float4*>(X + (size_t)row * DM);
    float4 v = xr[t];
    float s  = v.x + v.y + v.z + v.w;
    float s2 = v.x * v.x + v.y * v.y + v.z * v.z + v.w * v.w;
    __shared__ float rs[8], rs2[8];
#pragma unroll
    for (int o = 16; o > 0; o >>= 1) {
        s  += __shfl_xor_sync(0xffffffffu, s,  o);
        s2 += __shfl_xor_sync(0xffffffffu, s2, o);
    }
    if ((t & 31) == 0) { rs[t >> 5] = s; rs2[t >> 5] = s2; }
    __syncthreads();
    float S = 0.f, S2 = 0.f;
#pragma unroll
    for (int i = 0; i < 8; i++) { S += rs[i]; S2 += rs2[i]; }
    float mu  = S * (1.0f / DM);
    float var = S2 * (1.0f / DM) - mu * mu;
    float inv = rsqrtf(var + 1e-4f);
    float4 wv = reinterpret_cast<const float4*>(w)[t];
    float4 bv = reinterpret_cast<const float4*>(b)[t];
    float4 o;
    o.x = tf32f((v.x - mu) * inv * wv.x + bv.x);
    o.y = tf32f((v.y - mu) * inv * wv.y + bv.y);
    o.z = tf32f((v.z - mu) * inv * wv.z + bv.z);
    o.w = tf32f((v.w - mu) * inv * wv.w + bv.w);
    reinterpret_cast<float4*>(out + (size_t)row * DM)[t] = o;
}

// ---------------------------------------------------------------------------
// One launch: RNE-round all four weight matrices into g_Wr
// ---------------------------------------------------------------------------
__global__ void __launch_bounds__(256)
round4_tf32(const float* __restrict__ W0, const float* __restrict__ W1,
            const float* __restrict__ W2, const float* __restrict__ W3,
            float* __restrict__ R) {
    int i = blockIdx.x * 256 + threadIdx.x;       // float4 index
    int which = i >> 18;                          // DM*DM/4 = 262144 per matrix
    int j = i & 262143;
    const float* W = (which == 0) ? W0 : (which == 1) ? W1 : (which == 2) ? W2 : W3;
    float4 v = reinterpret_cast<const float4*>(W)[j];
    float4 o = { tf32f(v.x), tf32f(v.y), tf32f(v.z), tf32f(v.w) };
    reinterpret_cast<float4*>(R)[i] = o;
}

// ---------------------------------------------------------------------------
// tf32 mma.sync GEMM, up to 3 (pre-rounded) weight matrices fused.
// C[4096,1024] = A @ W + bias. 128x128x32 tiles, 8 warps, cp.async dbl buffer.
// ---------------------------------------------------------------------------
#define APAD 36
#define BPAD 136
#define A_ST (128 * APAD)
#define B_ST (32 * BPAD)
#define GEMM_SMEM ((2 * (A_ST + B_ST)) * 4)   // 71680 B

__global__ void __launch_bounds__(256)
gemm_mma3(const float* __restrict__ A,
          const float* __restrict__ W0, const float* __restrict__ W1,
          const float* __restrict__ W2,
          const float* __restrict__ bi0, const float* __restrict__ bi1,
          const float* __restrict__ bi2,
          float* __restrict__ C0, float* __restrict__ C1, float* __restrict__ C2) {
    extern __shared__ __align__(16) float sm[];
    float* Asm[2] = { sm, sm + A_ST };
    float* Bsm[2] = { sm + 2 * A_ST, sm + 2 * A_ST + B_ST };
    uint32_t aAddr[2] = { smem_u32(Asm[0]), smem_u32(Asm[1]) };
    uint32_t bAddr[2] = { smem_u32(Bsm[0]), smem_u32(Bsm[1]) };

    int nb = blockIdx.x;
    int sel = nb >> 3;
    int n0 = (nb & 7) * 128;
    const float* W    = (sel == 0) ? W0 : (sel == 1) ? W1 : W2;
    const float* bias = (sel == 0) ? bi0 : (sel == 1) ? bi1 : bi2;
    float* C          = (sel == 0) ? C0 : (sel == 1) ? C1 : C2;

    int tid = threadIdx.x, lane = tid & 31, wid = tid >> 5;
    int r = lane >> 2, cg = lane & 3;
    int wm = wid & 1, wn = wid >> 1;
    int m0 = blockIdx.y * 128;

    float acc[4][4][4];
#pragma unroll
    for (int i = 0; i < 4; i++)
#pragma unroll
        for (int j = 0; j < 4; j++)
#pragma unroll
            for (int k = 0; k < 4; k++) acc[i][j][k] = 0.f;

    auto load_tile = [&](int t, int buf) {
        int k0 = t * 32;
#pragma unroll
        for (int i = 0; i < 4; i++) {
            int idx = i * 256 + tid;
            int row = idx >> 3, c4 = (idx & 7) << 2;
            uint32_t dst = aAddr[buf] + (uint32_t)(row * APAD + c4) * 4u;
            CP_ASYNC16(dst, A + (size_t)(m0 + row) * DM + k0 + c4);
        }
#pragma unroll
        for (int i = 0; i < 4; i++) {
            int idx = i * 256 + tid;
            int row = idx >> 5, c4 = (idx & 31) << 2;
            uint32_t dst = bAddr[buf] + (uint32_t)(row * BPAD + c4) * 4u;
            CP_ASYNC16(dst, W + (size_t)(k0 + row) * DM + n0 + c4);
        }
        CP_COMMIT();
    };

    load_tile(0, 0);
    const int NT = DM / 32;
    for (int t = 0; t < NT; t++) {
        int buf = t & 1;
        if (t + 1 < NT) { load_tile(t + 1, (t + 1) & 1); CP_WAIT(1); }
        else            { CP_WAIT(0); }
        __syncthreads();

        const uint32_t* As = reinterpret_cast<const uint32_t*>(Asm[buf]);
        const uint32_t* Bs = reinterpret_cast<const uint32_t*>(Bsm[buf]);
#pragma unroll
        for (int kk = 0; kk < 4; kk++) {
            int kb = kk * 8;
            uint32_t aF[4][4];
#pragma unroll
            for (int mt = 0; mt < 4; mt++) {
                int mr = wm * 64 + mt * 16 + r;
                aF[mt][0] = As[mr * APAD + kb + cg];
                aF[mt][1] = As[(mr + 8) * APAD + kb + cg];
                aF[mt][2] = As[mr * APAD + kb + cg + 4];
                aF[mt][3] = As[(mr + 8) * APAD + kb + cg + 4];
            }
            uint32_t bF[4][2];
#pragma unroll
            for (int nt = 0; nt < 4; nt++) {
                int nc = wn * 32 + nt * 8 + r;
                bF[nt][0] = Bs[(kb + cg) * BPAD + nc];
                bF[nt][1] = Bs[(kb + cg + 4) * BPAD + nc];
            }
#pragma unroll
            for (int mt = 0; mt < 4; mt++)
#pragma unroll
                for (int nt = 0; nt < 4; nt++)
                    mma_tf32(acc[mt][nt], aF[mt], bF[nt][0], bF[nt][1]);
        }
        __syncthreads();
    }

    const float* bp = bias + n0 + wn * 32;
#pragma unroll
    for (int nt = 0; nt < 4; nt++) {
        float2 bb = *reinterpret_cast<const float2*>(bp + nt * 8 + 2 * cg);
#pragma unroll
        for (int mt = 0; mt < 4; mt++) {
            int row = m0 + wm * 64 + mt * 16 + r;
            float* c0 = C + (size_t)row * DM + n0 + wn * 32 + nt * 8 + 2 * cg;
            float* c1 = C + (size_t)(row + 8) * DM + n0 + wn * 32 + nt * 8 + 2 * cg;
            float2 v0 = { acc[mt][nt][0] + bb.x, acc[mt][nt][1] + bb.y };
            float2 v1 = { acc[mt][nt][2] + bb.x, acc[mt][nt][3] + bb.y };
            *reinterpret_cast<float2*>(c0) = v0;
            *reinterpret_cast<float2*>(c1) = v1;
        }
    }
}

// ---------------------------------------------------------------------------
// Flash attention, mma.sync tf32. 256 threads (8 warps), q-tile 128, k-tile 64.
// Single-buffered K/V (R4 config: 2 CTAs/SM residency beats intra-CTA pipeline).
// ---------------------------------------------------------------------------
#define ATT_PAD 68
#define ATTN_SMEM ((64 + 64 + 128) * ATT_PAD * 4)   // Ks, Vs, Ps = 69632 B

__global__ void __launch_bounds__(256, 2)
attn_mma(const float* __restrict__ Q, const float* __restrict__ K,
         const float* __restrict__ V, float* __restrict__ O) {
    extern __shared__ __align__(16) float sm[];
    float* Ks = sm;
    float* Vs = sm + 64 * ATT_PAD;
    float* Ps = sm + 2 * 64 * ATT_PAD;
    const uint32_t* KsU = reinterpret_cast<const uint32_t*>(Ks);
    const uint32_t* VsU = reinterpret_cast<const uint32_t*>(Vs);
    const uint32_t* PsU = reinterpret_cast<const uint32_t*>(Ps);

    int tid = threadIdx.x, lane = tid & 31, wid = tid >> 5;
    int qt = gridDim.x - 1 - blockIdx.x;          // heavy tiles first
    int bh = blockIdx.y;
    int b = bh >> 4, h = bh & 15, cb = h << 6;
    int qbase = b * SEQ + (qt << 7);
    int r = lane >> 2, cg = lane & 3;
    int qrow = (wid << 4) + r;                    // block-local 0..127 (+8)

    // Q fragments (scaled, tf32-rounded) — one-time load
    uint32_t aQ[8][4];
    const float* Q0 = Q + (size_t)(qbase + qrow) * DM + cb;
    const float* Q1 = Q + (size_t)(qbase + qrow + 8) * DM + cb;
#pragma unroll
    for (int kk = 0; kk < 8; kk++) {
        aQ[kk][0] = tf32u(Q0[kk * 8 + cg] * 0.125f);
        aQ[kk][1] = tf32u(Q1[kk * 8 + cg] * 0.125f);
        aQ[kk][2] = tf32u(Q0[kk * 8 + cg + 4] * 0.125f);
        aQ[kk][3] = tf32u(Q1[kk * 8 + cg + 4] * 0.125f);
    }

    float m0 = -INFINITY, m1 = -INFINITY, l0 = 0.f, l1 = 0.f;
    float oc[8][4];
#pragma unroll
    for (int i = 0; i < 8; i++)
#pragma unroll
        for (int j = 0; j < 4; j++) oc[i][j] = 0.f;

    int ktmax = 2 * qt + 1;
    for (int kt = 0; kt <= ktmax; kt++) {
        const float* Kg = K + (size_t)(b * SEQ + (kt << 6)) * DM + cb;
        const float* Vg = V + (size_t)(b * SEQ + (kt << 6)) * DM + cb;
        __syncthreads();   // previous iteration's Ks/Vs/Ps reads complete
#pragma unroll
        for (int i = 0; i < 4; i++) {
            int idx = i * 256 + tid;
            int row = idx >> 4, d4 = (idx & 15) << 2;
            float4 kv = *reinterpret_cast<const float4*>(Kg + (size_t)row * DM + d4);
            float4 vv = *reinterpret_cast<const float4*>(Vg + (size_t)row * DM + d4);
            float4 ko = { tf32f(kv.x), tf32f(kv.y), tf32f(kv.z), tf32f(kv.w) };
            float4 vo = { tf32f(vv.x), tf32f(vv.y), tf32f(vv.z), tf32f(vv.w) };
            *reinterpret_cast<float4*>(Ks + row * ATT_PAD + d4) = ko;
            *reinterpret_cast<float4*>(Vs + row * ATT_PAD + d4) = vo;
        }
        __syncthreads();

        // warps whose 16 rows are entirely above this k-tile: fully masked, skip
        bool active = ((kt << 6) <= (qt << 7) + (wid << 4) + 15);
        if (!active) continue;

        // S = Q K^T
        float sc[8][4];
#pragma unroll
        for (int nt = 0; nt < 8; nt++) {
#pragma unroll
            for (int j = 0; j < 4; j++) sc[nt][j] = 0.f;
#pragma unroll
            for (int kk = 0; kk < 8; kk++) {
                uint32_t b0 = KsU[(nt * 8 + r) * ATT_PAD + kk * 8 + cg];
                uint32_t b1 = KsU[(nt * 8 + r) * ATT_PAD + kk * 8 + cg + 4];
                mma_tf32(sc[nt], aQ[kk], b0, b1);
            }
        }

        // causal mask (q-local coords)
        int cofs = (kt << 6) - (qt << 7);
        if (cofs + 63 > qrow) {
#pragma unroll
            for (int nt = 0; nt < 8; nt++) {
                int col = cofs + nt * 8 + 2 * cg;
                if (col > qrow)         sc[nt][0] = -INFINITY;
                if (col + 1 > qrow)     sc[nt][1] = -INFINITY;
                if (col > qrow + 8)     sc[nt][2] = -INFINITY;
                if (col + 1 > qrow + 8) sc[nt][3] = -INFINITY;
            }
        }

        // online softmax, quad reduction
        float mx0 = -INFINITY, mx1 = -INFINITY;
#pragma unroll
        for (int nt = 0; nt < 8; nt++) {
            mx0 = fmaxf(mx0, fmaxf(sc[nt][0], sc[nt][1]));
            mx1 = fmaxf(mx1, fmaxf(sc[nt][2], sc[nt][3]));
        }
        mx0 = fmaxf(mx0, __shfl_xor_sync(0xffffffffu, mx0, 1));
        mx0 = fmaxf(mx0, __shfl_xor_sync(0xffffffffu, mx0, 2));
        mx1 = fmaxf(mx1, __shfl_xor_sync(0xffffffffu, mx1, 1));
        mx1 = fmaxf(mx1, __shfl_xor_sync(0xffffffffu, mx1, 2));
        float mn0 = fmaxf(m0, mx0), mn1 = fmaxf(m1, mx1);
        float e0 = __expf(m0 - mn0), e1 = __expf(m1 - mn1);
        float s0 = 0.f, s1 = 0.f;
#pragma unroll
        for (int nt = 0; nt < 8; nt++) {
            sc[nt][0] = __expf(sc[nt][0] - mn0);
            sc[nt][1] = __expf(sc[nt][1] - mn0);
            sc[nt][2] = __expf(sc[nt][2] - mn1);
            sc[nt][3] = __expf(sc[nt][3] - mn1);
            s0 += sc[nt][0] + sc[nt][1];
            s1 += sc[nt][2] + sc[nt][3];
        }
        s0 += __shfl_xor_sync(0xffffffffu, s0, 1);
        s0 += __shfl_xor_sync(0xffffffffu, s0, 2);
        s1 += __shfl_xor_sync(0xffffffffu, s1, 1);
        s1 += __shfl_xor_sync(0xffffffffu, s1, 2);
        l0 = l0 * e0 + s0; m0 = mn0;
        l1 = l1 * e1 + s1; m1 = mn1;
#pragma unroll
        for (int dt = 0; dt < 8; dt++) {
            oc[dt][0] *= e0; oc[dt][1] *= e0;
            oc[dt][2] *= e1; oc[dt][3] *= e1;
        }

        // stage P (tf32-rounded); warp-private rows -> __syncwarp suffices
#pragma unroll
        for (int nt = 0; nt < 8; nt++) {
            float2 p0 = { tf32f(sc[nt][0]), tf32f(sc[nt][1]) };
            float2 p1 = { tf32f(sc[nt][2]), tf32f(sc[nt][3]) };
            *reinterpret_cast<float2*>(Ps + qrow * ATT_PAD + nt * 8 + 2 * cg) = p0;
            *reinterpret_cast<float2*>(Ps + (qrow + 8) * ATT_PAD + nt * 8 + 2 * cg) = p1;
        }
        __syncwarp();

        // O += P @ V
#pragma unroll
        for (int kk = 0; kk < 8; kk++) {
            uint32_t aP[4];
            aP[0] = PsU[qrow * ATT_PAD + kk * 8 + cg];
            aP[1] = PsU[(qrow + 8) * ATT_PAD + kk * 8 + cg];
            aP[2] = PsU[qrow * ATT_PAD + kk * 8 + cg + 4];
            aP[3] = PsU[(qrow + 8) * ATT_PAD + kk * 8 + cg + 4];
#pragma unroll
            for (int dt = 0; dt < 8; dt++) {
                uint32_t b0 = VsU[(kk * 8 + cg) * ATT_PAD + dt * 8 + r];
                uint32_t b1 = VsU[(kk * 8 + cg + 4) * ATT_PAD + dt * 8 + r];
                mma_tf32(oc[dt], aP, b0, b1);
            }
        }
    }

    float inv0 = 1.0f / l0, inv1 = 1.0f / l1;
    float* O0 = O + (size_t)(qbase + qrow) * DM + cb;
    float* O1 = O + (size_t)(qbase + qrow + 8) * DM + cb;
#pragma unroll
    for (int dt = 0; dt < 8; dt++) {
        float2 v0 = { tf32f(oc[dt][0] * inv0), tf32f(oc[dt][1] * inv0) };
        float2 v1 = { tf32f(oc[dt][2] * inv1), tf32f(oc[dt][3] * inv1) };
        *reinterpret_cast<float2*>(O0 + dt * 8 + 2 * cg) = v0;
        *reinterpret_cast<float2*>(O1 + dt * 8 + 2 * cg) = v1;
    }
}

// ---------------------------------------------------------------------------
extern "C" void kernel_launch(void* const* d_in, const int* in_sizes, int n_in,
                              void* d_out, int out_size) {
    const float* X   = (const float*)d_in[0];
    const float* lnw = (const float*)d_in[1];
    const float* lnb = (const float*)d_in[2];
    const float* Wq  = (const float*)d_in[3];
    const float* bq  = (const float*)d_in[4];
    const float* Wk  = (const float*)d_in[5];
    const float* bk  = (const float*)d_in[6];
    const float* Wv  = (const float*)d_in[7];
    const float* bv  = (const float*)d_in[8];
    const float* Wo  = (const float*)d_in[9];
    const float* bo  = (const float*)d_in[10];
    float* out = (float*)d_out;
    (void)in_sizes; (void)n_in; (void)out_size;

    float *Xn, *Qb, *Kb, *Vb, *Mb, *Wr;
    cudaGetSymbolAddress((void**)&Xn, g_Xn);
    cudaGetSymbolAddress((void**)&Qb, g_Q);
    cudaGetSymbolAddress((void**)&Kb, g_K);
    cudaGetSymbolAddress((void**)&Vb, g_V);
    cudaGetSymbolAddress((void**)&Mb, g_M);
    cudaGetSymbolAddress((void**)&Wr, g_Wr);

    cudaFuncSetAttribute(gemm_mma3, cudaFuncAttributeMaxDynamicSharedMemorySize,
                         GEMM_SMEM);
    cudaFuncSetAttribute(attn_mma, cudaFuncAttributeMaxDynamicSharedMemorySize,
                         ATTN_SMEM);

    ln_kernel<<<NTOK, 256>>>(X, lnw, lnb, Xn);
    round4_tf32<<<4 * DM * DM / (256 * 4), 256>>>(Wq, Wk, Wv, Wo, Wr);

    // fused Q,K,V projections (pre-rounded weights)
    gemm_mma3<<<dim3(24, NTOK / 128), 256, GEMM_SMEM>>>(
        Xn, Wr, Wr + DM * DM, Wr + 2 * DM * DM, bq, bk, bv, Qb, Kb, Vb);

    attn_mma<<<dim3(SEQ / 128, 2 * NH), 256, ATTN_SMEM>>>(Qb, Kb, Vb, Mb);

    // output projection (sel always 0)
    gemm_mma3<<<dim3(8, NTOK / 128), 256, GEMM_SMEM>>>(
        Mb, Wr + 3 * DM * DM, Wr + 3 * DM * DM, Wr + 3 * DM * DM,
        bo, bo, bo, out, out, out);
}

// round 11
// speedup vs baseline: 1.1404x; 1.0766x over previous
#include <cuda_runtime.h>
#include <math.h>
#include <stdint.h>

#define DM   1024
#define NTOK 4096
#define SEQ  2048
#define NH   16

// Scratch buffers (allocation-free rule: __device__ globals).
__device__ float g_Xn[NTOK * DM];
__device__ float g_Q [NTOK * DM];
__device__ float g_K [NTOK * DM];
__device__ float g_V [NTOK * DM];
__device__ float g_M [NTOK * DM];
__device__ float g_Wr[4 * DM * DM];   // pre-rounded (tf32 RNE) Wq|Wk|Wv|Wo

// ---------------------------------------------------------------------------
// helpers
// ---------------------------------------------------------------------------
__device__ __forceinline__ uint32_t smem_u32(const void* p) {
    uint32_t a;
    asm("{ .reg .u64 t; cvta.to.shared.u64 t, %1; cvt.u32.u64 %0, t; }" : "=r"(a) : "l"(p));
    return a;
}
__device__ __forceinline__ uint32_t tf32u(float x) {
    uint32_t u; asm("cvt.rna.tf32.f32 %0, %1;" : "=r"(u) : "f"(x));
    return u;
}
__device__ __forceinline__ float tf32f(float x) { return __uint_as_float(tf32u(x)); }

__device__ __forceinline__ void mma_tf32(float* d, const uint32_t* a,
                                         uint32_t b0, uint32_t b1) {
    asm volatile(
        "mma.sync.aligned.m16n8k8.row.col.f32.tf32.tf32.f32 "
        "{%0,%1,%2,%3}, {%4,%5,%6,%7}, {%8,%9}, {%0,%1,%2,%3};"
        : "+f"(d[0]), "+f"(d[1]), "+f"(d[2]), "+f"(d[3])
        : "r"(a[0]), "r"(a[1]), "r"(a[2]), "r"(a[3]), "r"(b0), "r"(b1));
}

#define CP_ASYNC16(dst, src) \
    asm volatile("cp.async.cg.shared.global [%0], [%1], 16;" :: "r"(dst), "l"(src) : "memory")
#define CP_COMMIT() asm volatile("cp.async.commit_group;" ::: "memory")
#define CP_WAIT(n)  asm volatile("cp.async.wait_group %0;" :: "n"(n) : "memory")

// ---------------------------------------------------------------------------
// LayerNorm; output rounded to tf32 since it feeds tf32 MMAs.
// ---------------------------------------------------------------------------
__global__ void ln_kernel(const float* __restrict__ X, const float* __restrict__ w,
                          const float* __restrict__ b, float* __restrict__ out) {
    int row = blockIdx.x;
    int t = threadIdx.x;
    const float4* xr = reinterpret_cast<const float4*>(X + (size_t)row * DM);
    float4 v = xr[t];
    float s  = v.x + v.y + v.z + v.w;
    float s2 = v.x * v.x + v.y * v.y + v.z * v.z + v.w * v.w;
    __shared__ float rs[8], rs2[8];
#pragma unroll
    for (int o = 16; o > 0; o >>= 1) {
        s  += __shfl_xor_sync(0xffffffffu, s,  o);
        s2 += __shfl_xor_sync(0xffffffffu, s2, o);
    }
    if ((t & 31) == 0) { rs[t >> 5] = s; rs2[t >> 5] = s2; }
    __syncthreads();
    float S = 0.f, S2 = 0.f;
#pragma unroll
    for (int i = 0; i < 8; i++) { S += rs[i]; S2 += rs2[i]; }
    float mu  = S * (1.0f / DM);
    float var = S2 * (1.0f / DM) - mu * mu;
    float inv = rsqrtf(var + 1e-4f);
    float4 wv = reinterpret_cast<const float4*>(w)[t];
    float4 bv = reinterpret_cast<const float4*>(b)[t];
    float4 o;
    o.x = tf32f((v.x - mu) * inv * wv.x + bv.x);
    o.y = tf32f((v.y - mu) * inv * wv.y + bv.y);
    o.z = tf32f((v.z - mu) * inv * wv.z + bv.z);
    o.w = tf32f((v.w - mu) * inv * wv.w + bv.w);
    reinterpret_cast<float4*>(out + (size_t)row * DM)[t] = o;
}

// ---------------------------------------------------------------------------
// RNE-round all four weight matrices into g_Wr in one launch.
// ---------------------------------------------------------------------------
__global__ void __launch_bounds__(256)
round4_tf32(const float* __restrict__ W0, const float* __restrict__ W1,
            const float* __restrict__ W2, const float* __restrict__ W3,
            float* __restrict__ R) {
    int i = blockIdx.x * 256 + threadIdx.x;       // float4 index
    int which = i >> 18;                          // DM*DM/4 = 262144 per matrix
    int j = i & 262143;
    const float* W = (which == 0) ? W0 : (which == 1) ? W1 : (which == 2) ? W2 : W3;
    float4 v = reinterpret_cast<const float4*>(W)[j];
    float4 o = { tf32f(v.x), tf32f(v.y), tf32f(v.z), tf32f(v.w) };
    reinterpret_cast<float4*>(R)[i] = o;
}

// ---------------------------------------------------------------------------
// tf32 mma.sync GEMM, up to 3 (pre-rounded) weight matrices fused.
// C[4096,1024] = A @ W + bias. 128x128x32 tiles, 8 warps, cp.async dbl buffer.
// ---------------------------------------------------------------------------
#define APAD 36
#define BPAD 136
#define A_ST (128 * APAD)
#define B_ST (32 * BPAD)
#define GEMM_SMEM ((2 * (A_ST + B_ST)) * 4)   // 71680 B

__global__ void __launch_bounds__(256)
gemm_mma3(const float* __restrict__ A,
          const float* __restrict__ W0, const float* __restrict__ W1,
          const float* __restrict__ W2,
          const float* __restrict__ bi0, const float* __restrict__ bi1,
          const float* __restrict__ bi2,
          float* __restrict__ C0, float* __restrict__ C1, float* __restrict__ C2) {
    extern __shared__ __align__(16) float sm[];
    float* Asm[2] = { sm, sm + A_ST };
    float* Bsm[2] = { sm + 2 * A_ST, sm + 2 * A_ST + B_ST };
    uint32_t aAddr[2] = { smem_u32(Asm[0]), smem_u32(Asm[1]) };
    uint32_t bAddr[2] = { smem_u32(Bsm[0]), smem_u32(Bsm[1]) };

    int nb = blockIdx.x;
    int sel = nb >> 3;
    int n0 = (nb & 7) * 128;
    const float* W    = (sel == 0) ? W0 : (sel == 1) ? W1 : W2;
    const float* bias = (sel == 0) ? bi0 : (sel == 1) ? bi1 : bi2;
    float* C          = (sel == 0) ? C0 : (sel == 1) ? C1 : C2;

    int tid = threadIdx.x, lane = tid & 31, wid = tid >> 5;
    int r = lane >> 2, cg = lane & 3;
    int wm = wid & 1, wn = wid >> 1;
    int m0 = blockIdx.y * 128;

    float acc[4][4][4];
#pragma unroll
    for (int i = 0; i < 4; i++)
#pragma unroll
        for (int j = 0; j < 4; j++)
#pragma unroll
            for (int k = 0; k < 4; k++) acc[i][j][k] = 0.f;

    auto load_tile = [&](int t, int buf) {
        int k0 = t * 32;
#pragma unroll
        for (int i = 0; i < 4; i++) {
            int idx = i * 256 + tid;
            int row = idx >> 3, c4 = (idx & 7) << 2;
            uint32_t dst = aAddr[buf] + (uint32_t)(row * APAD + c4) * 4u;
            CP_ASYNC16(dst, A + (size_t)(m0 + row) * DM + k0 + c4);
        }
#pragma unroll
        for (int i = 0; i < 4; i++) {
            int idx = i * 256 + tid;
            int row = idx >> 5, c4 = (idx & 31) << 2;
            uint32_t dst = bAddr[buf] + (uint32_t)(row * BPAD + c4) * 4u;
            CP_ASYNC16(dst, W + (size_t)(k0 + row) * DM + n0 + c4);
        }
        CP_COMMIT();
    };

    load_tile(0, 0);
    const int NT = DM / 32;
    for (int t = 0; t < NT; t++) {
        int buf = t & 1;
        if (t + 1 < NT) { load_tile(t + 1, (t + 1) & 1); CP_WAIT(1); }
        else            { CP_WAIT(0); }
        __syncthreads();

        const uint32_t* As = reinterpret_cast<const uint32_t*>(Asm[buf]);
        const uint32_t* Bs = reinterpret_cast<const uint32_t*>(Bsm[buf]);
#pragma unroll
        for (int kk = 0; kk < 4; kk++) {
            int kb = kk * 8;
            uint32_t aF[4][4];
#pragma unroll
            for (int mt = 0; mt < 4; mt++) {
                int mr = wm * 64 + mt * 16 + r;
                aF[mt][0] = As[mr * APAD + kb + cg];
                aF[mt][1] = As[(mr + 8) * APAD + kb + cg];
                aF[mt][2] = As[mr * APAD + kb + cg + 4];
                aF[mt][3] = As[(mr + 8) * APAD + kb + cg + 4];
            }
            uint32_t bF[4][2];
#pragma unroll
            for (int nt = 0; nt < 4; nt++) {
                int nc = wn * 32 + nt * 8 + r;
                bF[nt][0] = Bs[(kb + cg) * BPAD + nc];
                bF[nt][1] = Bs[(kb + cg + 4) * BPAD + nc];
            }
#pragma unroll
            for (int mt = 0; mt < 4; mt++)
#pragma unroll
                for (int nt = 0; nt < 4; nt++)
                    mma_tf32(acc[mt][nt], aF[mt], bF[nt][0], bF[nt][1]);
        }
        __syncthreads();
    }

    const float* bp = bias + n0 + wn * 32;
#pragma unroll
    for (int nt = 0; nt < 4; nt++) {
        float2 bb = *reinterpret_cast<const float2*>(bp + nt * 8 + 2 * cg);
#pragma unroll
        for (int mt = 0; mt < 4; mt++) {
            int row = m0 + wm * 64 + mt * 16 + r;
            float* c0 = C + (size_t)row * DM + n0 + wn * 32 + nt * 8 + 2 * cg;
            float* c1 = C + (size_t)(row + 8) * DM + n0 + wn * 32 + nt * 8 + 2 * cg;
            float2 v0 = { acc[mt][nt][0] + bb.x, acc[mt][nt][1] + bb.y };
            float2 v1 = { acc[mt][nt][2] + bb.x, acc[mt][nt][3] + bb.y };
            *reinterpret_cast<float2*>(c0) = v0;
            *reinterpret_cast<float2*>(c1) = v1;
        }
    }
}

// ---------------------------------------------------------------------------
// Flash attention, mma.sync tf32. 128 threads (4 warps), q-tile 64, k-tile 64.
// 4 CTAs/SM (52KB smem, regs capped at 128): cross-CTA overlap hides the
// staging phase. Softmax runs in exp2 domain (log2e folded into Q scale).
// ---------------------------------------------------------------------------
#define ATT_PAD 68
#define ATTN_SMEM (3 * 64 * ATT_PAD * 4)   // Ks, Vs, Ps = 52224 B
#define QSCALE (0.125f * 1.44269504f)      // (1/sqrt(64)) * log2(e)

__global__ void __launch_bounds__(128, 4)
attn_mma_q64(const float* __restrict__ Q, const float* __restrict__ K,
             const float* __restrict__ V, float* __restrict__ O) {
    extern __shared__ __align__(16) float sm[];
    float* Ks = sm;
    float* Vs = sm + 64 * ATT_PAD;
    float* Ps = sm + 2 * 64 * ATT_PAD;
    const uint32_t* KsU = reinterpret_cast<const uint32_t*>(Ks);
    const uint32_t* VsU = reinterpret_cast<const uint32_t*>(Vs);
    const uint32_t* PsU = reinterpret_cast<const uint32_t*>(Ps);

    int tid = threadIdx.x, lane = tid & 31, wid = tid >> 5;
    int qt = gridDim.x - 1 - blockIdx.x;          // heavy q-tiles launch first
    int bh = blockIdx.y;
    int b = bh >> 4, h = bh & 15, cb = h << 6;
    int qbase = b * SEQ + (qt << 6);
    int r = lane >> 2, cg = lane & 3;
    int qrow = (wid << 4) + r;                    // block-local row 0..63 (+8)

    // One-time Q fragment load (scaled by QSCALE, tf32 RNE).
    uint32_t aQ[8][4];
    const float* Q0 = Q + (size_t)(qbase + qrow) * DM + cb;
    const float* Q1 = Q + (size_t)(qbase + qrow + 8) * DM + cb;
#pragma unroll
    for (int kk = 0; kk < 8; kk++) {
        aQ[kk][0] = tf32u(Q0[kk * 8 + cg] * QSCALE);
        aQ[kk][1] = tf32u(Q1[kk * 8 + cg] * QSCALE);
        aQ[kk][2] = tf32u(Q0[kk * 8 + cg + 4] * QSCALE);
        aQ[kk][3] = tf32u(Q1[kk * 8 + cg + 4] * QSCALE);
    }

    float m0 = -INFINITY, m1 = -INFINITY, l0 = 0.f, l1 = 0.f;
    float oc[8][4];
#pragma unroll
    for (int i = 0; i < 8; i++)
#pragma unroll
        for (int j = 0; j < 4; j++) oc[i][j] = 0.f;

    for (int kt = 0; kt <= qt; kt++) {
        const float* Kg = K + (size_t)(b * SEQ + (kt << 6)) * DM + cb;
        const float* Vg = V + (size_t)(b * SEQ + (kt << 6)) * DM + cb;
        __syncthreads();    // prior iteration's Ks/Vs reads complete
#pragma unroll
        for (int i = 0; i < 8; i++) {
            int idx = i * 128 + tid;
            int row = idx >> 4, d4 = (idx & 15) << 2;
            float4 kv = *reinterpret_cast<const float4*>(Kg + (size_t)row * DM + d4);
            float4 vv = *reinterpret_cast<const float4*>(Vg + (size_t)row * DM + d4);
            float4 ko = { tf32f(kv.x), tf32f(kv.y), tf32f(kv.z), tf32f(kv.w) };
            float4 vo = { tf32f(vv.x), tf32f(vv.y), tf32f(vv.z), tf32f(vv.w) };
            *reinterpret_cast<float4*>(Ks + row * ATT_PAD + d4) = ko;
            *reinterpret_cast<float4*>(Vs + row * ATT_PAD + d4) = vo;
        }
        __syncthreads();

        // S = Q K^T (already log2-scaled via QSCALE)
        float sc[8][4];
#pragma unroll
        for (int nt = 0; nt < 8; nt++) {
#pragma unroll
            for (int j = 0; j < 4; j++) sc[nt][j] = 0.f;
#pragma unroll
            for (int kk = 0; kk < 8; kk++) {
                uint32_t b0 = KsU[(nt * 8 + r) * ATT_PAD + kk * 8 + cg];
                uint32_t b1 = KsU[(nt * 8 + r) * ATT_PAD + kk * 8 + cg + 4];
                mma_tf32(sc[nt], aQ[kk], b0, b1);
            }
        }

        if (kt == qt) {
#pragma unroll
            for (int nt = 0; nt < 8; nt++) {
                int col = nt * 8 + 2 * cg;
                if (col > qrow)         sc[nt][0] = -INFINITY;
                if (col + 1 > qrow)     sc[nt][1] = -INFINITY;
                if (col > qrow + 8)     sc[nt][2] = -INFINITY;
                if (col + 1 > qrow + 8) sc[nt][3] = -INFINITY;
            }
        }

        // Online softmax in exp2 domain; quad (4-lane) reductions per row.
        float mx0 = -INFINITY, mx1 = -INFINITY;
#pragma unroll
        for (int nt = 0; nt < 8; nt++) {
            mx0 = fmaxf(mx0, fmaxf(sc[nt][0], sc[nt][1]));
            mx1 = fmaxf(mx1, fmaxf(sc[nt][2], sc[nt][3]));
        }
        mx0 = fmaxf(mx0, __shfl_xor_sync(0xffffffffu, mx0, 1));
        mx0 = fmaxf(mx0, __shfl_xor_sync(0xffffffffu, mx0, 2));
        mx1 = fmaxf(mx1, __shfl_xor_sync(0xffffffffu, mx1, 1));
        mx1 = fmaxf(mx1, __shfl_xor_sync(0xffffffffu, mx1, 2));
        float mn0 = fmaxf(m0, mx0), mn1 = fmaxf(m1, mx1);
        float e0 = exp2f(m0 - mn0), e1 = exp2f(m1 - mn1);
        float s0 = 0.f, s1 = 0.f;
#pragma unroll
        for (int nt = 0; nt < 8; nt++) {
            sc[nt][0] = exp2f(sc[nt][0] - mn0);
            sc[nt][1] = exp2f(sc[nt][1] - mn0);
            sc[nt][2] = exp2f(sc[nt][2] - mn1);
            sc[nt][3] = exp2f(sc[nt][3] - mn1);
            s0 += sc[nt][0] + sc[nt][1];
            s1 += sc[nt][2] + sc[nt][3];
        }
        s0 += __shfl_xor_sync(0xffffffffu, s0, 1);
        s0 += __shfl_xor_sync(0xffffffffu, s0, 2);
        s1 += __shfl_xor_sync(0xffffffffu, s1, 1);
        s1 += __shfl_xor_sync(0xffffffffu, s1, 2);
        l0 = l0 * e0 + s0; m0 = mn0;
        l1 = l1 * e1 + s1; m1 = mn1;
#pragma unroll
        for (int dt = 0; dt < 8; dt++) {
            oc[dt][0] *= e0; oc[dt][1] *= e0;
            oc[dt][2] *= e1; oc[dt][3] *= e1;
        }

        // Stage P (tf32 RNE). Rows are warp-private, so __syncwarp suffices.
#pragma unroll
        for (int nt = 0; nt < 8; nt++) {
            float2 p0 = { tf32f(sc[nt][0]), tf32f(sc[nt][1]) };
            float2 p1 = { tf32f(sc[nt][2]), tf32f(sc[nt][3]) };
            *reinterpret_cast<float2*>(Ps + qrow * ATT_PAD + nt * 8 + 2 * cg) = p0;
            *reinterpret_cast<float2*>(Ps + (qrow + 8) * ATT_PAD + nt * 8 + 2 * cg) = p1;
        }
        __syncwarp();

        // O += P @ V
#pragma unroll
        for (int kk = 0; kk < 8; kk++) {
            uint32_t aP[4];
            aP[0] = PsU[qrow * ATT_PAD + kk * 8 + cg];
            aP[1] = PsU[(qrow + 8) * ATT_PAD + kk * 8 + cg];
            aP[2] = PsU[qrow * ATT_PAD + kk * 8 + cg + 4];
            aP[3] = PsU[(qrow + 8) * ATT_PAD + kk * 8 + cg + 4];
#pragma unroll
            for (int dt = 0; dt < 8; dt++) {
                uint32_t b0 = VsU[(kk * 8 + cg) * ATT_PAD + dt * 8 + r];
                uint32_t b1 = VsU[(kk * 8 + cg + 4) * ATT_PAD + dt * 8 + r];
                mma_tf32(oc[dt], aP, b0, b1);
            }
        }
    }

    float inv0 = 1.0f / l0, inv1 = 1.0f / l1;
    float* O0 = O + (size_t)(qbase + qrow) * DM + cb;
    float* O1 = O + (size_t)(qbase + qrow + 8) * DM + cb;
#pragma unroll
    for (int dt = 0; dt < 8; dt++) {
        float2 v0 = { tf32f(oc[dt][0] * inv0), tf32f(oc[dt][1] * inv0) };
        float2 v1 = { tf32f(oc[dt][2] * inv1), tf32f(oc[dt][3] * inv1) };
        *reinterpret_cast<float2*>(O0 + dt * 8 + 2 * cg) = v0;
        *reinterpret_cast<float2*>(O1 + dt * 8 + 2 * cg) = v1;
    }
}

// ---------------------------------------------------------------------------
extern "C" void kernel_launch(void* const* d_in, const int* in_sizes, int n_in,
                              void* d_out, int out_size) {
    const float* X   = (const float*)d_in[0];
    const float* lnw = (const float*)d_in[1];
    const float* lnb = (const float*)d_in[2];
    const float* Wq  = (const float*)d_in[3];
    const float* bq  = (const float*)d_in[4];
    const float* Wk  = (const float*)d_in[5];
    const float* bk  = (const float*)d_in[6];
    const float* Wv  = (const float*)d_in[7];
    const float* bv  = (const float*)d_in[8];
    const float* Wo  = (const float*)d_in[9];
    const float* bo  = (const float*)d_in[10];
    float* out = (float*)d_out;
    (void)in_sizes; (void)n_in; (void)out_size;

    float *Xn, *Qb, *Kb, *Vb, *Mb, *Wr;
    cudaGetSymbolAddress((void**)&Xn, g_Xn);
    cudaGetSymbolAddress((void**)&Qb, g_Q);
    cudaGetSymbolAddress((void**)&Kb, g_K);
    cudaGetSymbolAddress((void**)&Vb, g_V);
    cudaGetSymbolAddress((void**)&Mb, g_M);
    cudaGetSymbolAddress((void**)&Wr, g_Wr);

    cudaFuncSetAttribute(gemm_mma3, cudaFuncAttributeMaxDynamicSharedMemorySize,
                         GEMM_SMEM);
    cudaFuncSetAttribute(attn_mma_q64, cudaFuncAttributeMaxDynamicSharedMemorySize,
                         ATTN_SMEM);

    ln_kernel<<<NTOK, 256>>>(X, lnw, lnb, Xn);
    round4_tf32<<<4 * DM * DM / (256 * 4), 256>>>(Wq, Wk, Wv, Wo, Wr);

    // Fused Q,K,V projections (pre-rounded weights).
    gemm_mma3<<<dim3(24, NTOK / 128), 256, GEMM_SMEM>>>(
        Xn, Wr, Wr + DM * DM, Wr + 2 * DM * DM, bq, bk, bv, Qb, Kb, Vb);

    attn_mma_q64<<<dim3(SEQ / 64, 2 * NH), 128, ATTN_SMEM>>>(Qb, Kb, Vb, Mb);

    // Output projection (sel always 0).
    gemm_mma3<<<dim3(8, NTOK / 128), 256, GEMM_SMEM>>>(
        Mb, Wr + 3 * DM * DM, Wr + 3 * DM * DM, Wr + 3 * DM * DM,
        bo, bo, bo, out, out, out);
}